// round 5
// baseline (speedup 1.0000x reference)
#include <cuda_runtime.h>
#include <cstdint>

#define IN_DIM   4096
#define OUT_DIM  1024
#define N_ROWS   16384
#define NCH      8
#define CCOLS    512                 // columns per K-chunk
#define TILE_N   64                  // x rows per CTA (2 per lane)
#define SLOT     32                  // entry slots per (row,chunk)
#define COLF     66                  // floats per column in x-tile (64 rows + pad)
#define X2_BYTES (513 * COLF * 4)    // 135432: 512 data cols + 1 zero (dummy) col
#define E0_OFF   135456              // entry table offset (16B aligned)
#define ENT_BYTES (512 * SLOT * 4)   // 65536
#define CNT_OFF  (E0_OFF + ENT_BYTES)
#define SMEM_TOTAL (CNT_OFF + 1024)  // 202016 bytes
#define THREADS  512

// entry = local_col * 264  (byte offset of column in x-tile); dummy = 512*264 (zero col)
__device__ uint32_t g_ce[NCH * OUT_DIM * SLOT];
__device__ uint16_t g_sc[NCH * OUT_DIM];   // (pos_batches) | (neg_batches << 8), batches of 2
__device__ float    g_mag;

// ---------------------------------------------------------------------------
// Build: one warp per output row. Per (row, chunk): positives then negatives,
// each padded to even count with dummy entries. Deterministic.
// ---------------------------------------------------------------------------
__global__ void __launch_bounds__(256) build_csr(const float* __restrict__ Phi) {
    const int row  = blockIdx.x * 8 + (threadIdx.x >> 5);
    const int lane = threadIdx.x & 31;
    if (row >= OUT_DIM) return;
    const float* pr = Phi + (size_t)row * IN_DIM;

    for (int k = 0; k < NCH; ++k) {
        uint32_t* slot = g_ce + (size_t)(k * OUT_DIM + row) * SLOT;
        int pos = 0, cp = 0;
        #pragma unroll
        for (int sgn = 0; sgn < 2; ++sgn) {
            for (int c0 = k * CCOLS; c0 < (k + 1) * CCOLS; c0 += 32) {
                float v = pr[c0 + lane];
                bool nz = sgn ? (v < 0.0f) : (v > 0.0f);
                unsigned m = __ballot_sync(0xffffffffu, nz);
                if (nz) {
                    int p = pos + __popc(m & ((1u << lane) - 1u));
                    if (p < SLOT) slot[p] = (uint32_t)((c0 + lane) & (CCOLS - 1)) * 264u;
                    g_mag = fabsf(v);   // same value from all writers
                }
                pos += __popc(m);
            }
            if (pos & 1) {              // pad to even
                if (lane == 0 && pos < SLOT) slot[pos] = CCOLS * 264u;
                pos++;
            }
            if (pos > SLOT) pos = SLOT; // statistically unreachable clamp
            if (sgn == 0) cp = pos;
        }
        int cn = pos - cp;
        if (lane == 0) g_sc[k * OUT_DIM + row] = (uint16_t)((cp >> 1) | ((cn >> 1) << 8));
    }
}

// ---------------------------------------------------------------------------
// Main: CTA = (64 x-rows, 512 out-rows). Lane n holds x-rows (2n, 2n+1).
// x-tile col-major float2; entries staged in smem; FFMA vs +/-mag registers.
// ---------------------------------------------------------------------------
__global__ void __launch_bounds__(THREADS, 1) jl_main(const float* __restrict__ x,
                                                      float* __restrict__ out) {
    extern __shared__ char sm[];
    float* xf = (float*)sm;
    const int tid  = threadIdx.x;
    const int lane = tid & 31;
    const int w    = tid >> 5;              // 16 warps, warp owns 32 out-rows
    const int n0   = blockIdx.x * TILE_N;
    const int rb   = blockIdx.y * 512;      // out-row half

    const float pm = g_mag, nm = -pm;
    const char* xb = sm + lane * 8;         // this lane's row-pair base

    if (tid < COLF) xf[CCOLS * COLF + tid] = 0.0f;   // zero dummy column

    float2 acc[32];
    #pragma unroll
    for (int i = 0; i < 32; ++i) acc[i] = make_float2(0.0f, 0.0f);

    for (int k = 0; k < NCH; ++k) {
        __syncthreads();
        // Stage x: 64 rows x 512 cols, scalar (coalesced LDG, 2-way STS conflicts)
        #pragma unroll 4
        for (int i = tid; i < TILE_N * CCOLS; i += THREADS) {
            int row = i >> 9;
            int c   = i & (CCOLS - 1);
            xf[c * COLF + row] =
                x[(size_t)(n0 + row) * IN_DIM + k * CCOLS + c];
        }
        // Stage entry slots for this CTA's 512 rows (64 KB, vectorized)
        {
            const uint4* src = (const uint4*)(g_ce + (size_t)(k * OUT_DIM + rb) * SLOT);
            uint4* dst = (uint4*)(sm + E0_OFF);
            #pragma unroll 2
            for (int i = tid; i < ENT_BYTES / 16; i += THREADS) dst[i] = src[i];
        }
        if (tid < 512)
            *(uint16_t*)(sm + CNT_OFF + tid * 2) = g_sc[k * OUT_DIM + rb + tid];
        __syncthreads();

        // Sweep this warp's 32 out-rows
        #pragma unroll
        for (int rr = 0; rr < 32; ++rr) {
            const int idx = w * 32 + rr;
            const unsigned cnts = *(const uint16_t*)(sm + CNT_OFF + idx * 2);
            const char* eb = sm + E0_OFF + idx * (SLOT * 4);
            int np = cnts & 0xFFu, nn = cnts >> 8;
            float2 a = acc[rr];
            for (int b = 0; b < np; ++b) {           // positive entries, pairs
                uint2 e = *(const uint2*)eb; eb += 8;
                float2 f0 = *(const float2*)(xb + e.x);
                float2 f1 = *(const float2*)(xb + e.y);
                a.x = fmaf(f0.x, pm, a.x); a.y = fmaf(f0.y, pm, a.y);
                a.x = fmaf(f1.x, pm, a.x); a.y = fmaf(f1.y, pm, a.y);
            }
            for (int b = 0; b < nn; ++b) {           // negative entries, pairs
                uint2 e = *(const uint2*)eb; eb += 8;
                float2 f0 = *(const float2*)(xb + e.x);
                float2 f1 = *(const float2*)(xb + e.y);
                a.x = fmaf(f0.x, nm, a.x); a.y = fmaf(f0.y, nm, a.y);
                a.x = fmaf(f1.x, nm, a.x); a.y = fmaf(f1.y, nm, a.y);
            }
            acc[rr] = a;
        }
    }

    // Output: stage via smem (reuses x-tile region), then coalesced store
    __syncthreads();
    #pragma unroll
    for (int rr = 0; rr < 32; ++rr) {
        const int idx = w * 32 + rr;
        xf[(2 * lane)     * 513 + idx] = acc[rr].x;
        xf[(2 * lane + 1) * 513 + idx] = acc[rr].y;
    }
    __syncthreads();
    #pragma unroll 4
    for (int i = tid; i < TILE_N * 512; i += THREADS) {
        int row = i >> 9;
        int c   = i & 511;
        out[(size_t)(n0 + row) * OUT_DIM + rb + c] = xf[row * 513 + c];
    }
}

// ---------------------------------------------------------------------------
extern "C" void kernel_launch(void* const* d_in, const int* in_sizes, int n_in,
                              void* d_out, int out_size) {
    const float* x   = (const float*)d_in[0];
    const float* Phi = (const float*)d_in[1];
    if (n_in >= 2 && in_sizes[0] == OUT_DIM * IN_DIM &&
        in_sizes[1] == N_ROWS * IN_DIM) {
        x   = (const float*)d_in[1];
        Phi = (const float*)d_in[0];
    }
    float* out = (float*)d_out;

    build_csr<<<OUT_DIM / 8, 256>>>(Phi);

    cudaFuncSetAttribute(jl_main, cudaFuncAttributeMaxDynamicSharedMemorySize,
                         SMEM_TOTAL);
    jl_main<<<dim3(N_ROWS / TILE_N, 2), THREADS, SMEM_TOTAL>>>(x, out);
}

// round 6
// speedup vs baseline: 2.1852x; 2.1852x over previous
#include <cuda_runtime.h>
#include <cstdint>

#define IN_DIM   4096
#define OUT_DIM  1024
#define N_ROWS   16384
#define NCH      16
#define CCOLS    256                  // columns per K-chunk
#define TILE_N   128                  // x rows per CTA (4 per lane)
#define XSTRIDE  132                  // words per column (128 rows + 4 pad)
#define DUMMY_OFF (CCOLS * XSTRIDE * 4)   // 135168: zero column byte offset
#define XS_WORDS  ((CCOLS + 1) * XSTRIDE) // 33924 words = 135696 B
#define SMEM_BYTES (XS_WORDS * 4)
#define OUT_STRIDE 257                // out-staging row stride (words)
#define MAX_E    128
#define THREADS  1024                 // 32 warps -> regs hard-capped at 64 (no spill room needed)
#define RPC      256                  // out-rows per CTA (grid.y = 4)
#define RPW      8                    // out-rows per warp -> float4 acc[8] = 32 regs

// entry = local_col * 528 (byte offset of column in x-tile) | sign<<31 ; dummy -> zero col
__device__ uint32_t g_ents[OUT_DIM * MAX_E];
__device__ uint16_t g_seg[NCH * OUT_DIM];  // startPair | (pairCnt << 8)
__device__ float    g_mag;

// ---------------------------------------------------------------------------
// Build: one warp per output row; per-chunk segments padded to even length.
// Deterministic (ballot/popc in column order).
// ---------------------------------------------------------------------------
__global__ void __launch_bounds__(256) build_csr(const float* __restrict__ Phi) {
    const int row  = blockIdx.x * 8 + (threadIdx.x >> 5);
    const int lane = threadIdx.x & 31;
    if (row >= OUT_DIM) return;
    const float* pr = Phi + (size_t)row * IN_DIM;
    uint32_t* er = g_ents + row * MAX_E;

    int pos = 0;
    for (int k = 0; k < NCH; ++k) {
        const int start = pos;               // even by induction
        for (int c0 = k * CCOLS; c0 < (k + 1) * CCOLS; c0 += 32) {
            float v = pr[c0 + lane];
            unsigned m = __ballot_sync(0xffffffffu, v != 0.0f);
            if (v != 0.0f) {
                int p = pos + __popc(m & ((1u << lane) - 1u));
                if (p < MAX_E)
                    er[p] = (uint32_t)((c0 + lane) & (CCOLS - 1)) * (XSTRIDE * 4)
                          | (__float_as_uint(v) & 0x80000000u);
                g_mag = fabsf(v);            // identical value from every writer
            }
            pos += __popc(m);
        }
        if (pos & 1) {                       // pad to even with dummy (zero col, +sign)
            if (lane == 0 && pos < MAX_E) er[pos] = DUMMY_OFF;
            pos++;
        }
        if (pos > MAX_E) pos = MAX_E;        // statistically unreachable clamp
        int pairs = (pos - start) >> 1;
        if (lane == 0)
            g_seg[k * OUT_DIM + row] = (uint16_t)((start >> 1) | (pairs << 8));
    }
}

// ---------------------------------------------------------------------------
// Main: CTA = (128 x-rows, 256 out-rows). Lane n holds rows 4n..4n+3 (float4).
// x-tile col-major (stride 132 words). Warp w owns 8 out-rows, acc in regs.
// ---------------------------------------------------------------------------
__global__ void __launch_bounds__(THREADS, 1) jl_main(const float* __restrict__ x,
                                                      float* __restrict__ out) {
    extern __shared__ float xs[];
    const int tid  = threadIdx.x;
    const int lane = tid & 31;            // row-quad id
    const int w    = tid >> 5;            // warp 0..31
    const int n0   = blockIdx.x * TILE_N;
    const int rb   = blockIdx.y * RPC;
    const int r0   = rb + w * RPW;

    const unsigned magbits = __float_as_uint(g_mag);
    const char* xb = (const char*)xs + lane * 16;

    if (tid < XSTRIDE) xs[CCOLS * XSTRIDE + tid] = 0.0f;   // zero dummy column

    float4 acc[RPW];
    #pragma unroll
    for (int i = 0; i < RPW; ++i) acc[i] = make_float4(0.f, 0.f, 0.f, 0.f);

    for (int k = 0; k < NCH; ++k) {
        __syncthreads();
        // Stage x chunk: warp w handles col-quads {w, w+32}; lane = row-quad.
        // 4x LDG.128 (4 rows x 4 cols) -> register transpose -> 4x conflict-free STS.128.
        #pragma unroll
        for (int it = 0; it < 2; ++it) {
            const int cq = w + it * 32;
            const float* src = x + (size_t)(n0 + 4 * lane) * IN_DIM + k * CCOLS + 4 * cq;
            float4 v0 = *(const float4*)(src);
            float4 v1 = *(const float4*)(src + IN_DIM);
            float4 v2 = *(const float4*)(src + 2 * IN_DIM);
            float4 v3 = *(const float4*)(src + 3 * IN_DIM);
            float* d = xs + (4 * cq) * XSTRIDE + 4 * lane;
            *(float4*)(d)               = make_float4(v0.x, v1.x, v2.x, v3.x);
            *(float4*)(d + XSTRIDE)     = make_float4(v0.y, v1.y, v2.y, v3.y);
            *(float4*)(d + 2 * XSTRIDE) = make_float4(v0.z, v1.z, v2.z, v3.z);
            *(float4*)(d + 3 * XSTRIDE) = make_float4(v0.w, v1.w, v2.w, v3.w);
        }
        __syncthreads();

        // All 8 row-segments' metadata in one 16B load (warp-uniform)
        const uint4 segw = __ldg((const uint4*)(g_seg + k * OUT_DIM + r0));
        uint32_t segs[4] = {segw.x, segw.y, segw.z, segw.w};

        #pragma unroll
        for (int rr = 0; rr < RPW; ++rr) {
            const unsigned s16 = (segs[rr >> 1] >> ((rr & 1) * 16)) & 0xFFFFu;
            const uint2* ep = (const uint2*)(g_ents + ((r0 + rr) << 7)) + (s16 & 0xFFu);
            const int pairs = (int)(s16 >> 8);
            float4 a = acc[rr];
            for (int p = 0; p < pairs; ++p) {
                const uint2 e = __ldg(ep + p);
                {
                    float m0 = __uint_as_float(magbits | (e.x & 0x80000000u));
                    float4 f = *(const float4*)(xb + (e.x & 0x0003FFFFu));
                    a.x = fmaf(f.x, m0, a.x); a.y = fmaf(f.y, m0, a.y);
                    a.z = fmaf(f.z, m0, a.z); a.w = fmaf(f.w, m0, a.w);
                }
                {
                    float m1 = __uint_as_float(magbits | (e.y & 0x80000000u));
                    float4 f = *(const float4*)(xb + (e.y & 0x0003FFFFu));
                    a.x = fmaf(f.x, m1, a.x); a.y = fmaf(f.y, m1, a.y);
                    a.z = fmaf(f.z, m1, a.z); a.w = fmaf(f.w, m1, a.w);
                }
            }
            acc[rr] = a;
        }
    }

    // Stage outputs (stride-257 kills bank conflicts), then coalesced float4 STG
    __syncthreads();
    #pragma unroll
    for (int rr = 0; rr < RPW; ++rr) {
        const int rl = w * RPW + rr;
        float4 a = acc[rr];
        xs[(4 * lane + 0) * OUT_STRIDE + rl] = a.x;
        xs[(4 * lane + 1) * OUT_STRIDE + rl] = a.y;
        xs[(4 * lane + 2) * OUT_STRIDE + rl] = a.z;
        xs[(4 * lane + 3) * OUT_STRIDE + rl] = a.w;
    }
    __syncthreads();
    {
        const int mq = tid & 63;          // 64 col-quads cover 256 r
        #pragma unroll
        for (int row = tid >> 6; row < TILE_N; row += 16) {
            float4 v;
            v.x = xs[row * OUT_STRIDE + 4 * mq + 0];
            v.y = xs[row * OUT_STRIDE + 4 * mq + 1];
            v.z = xs[row * OUT_STRIDE + 4 * mq + 2];
            v.w = xs[row * OUT_STRIDE + 4 * mq + 3];
            *(float4*)(out + (size_t)(n0 + row) * OUT_DIM + rb + 4 * mq) = v;
        }
    }
}

// ---------------------------------------------------------------------------
extern "C" void kernel_launch(void* const* d_in, const int* in_sizes, int n_in,
                              void* d_out, int out_size) {
    const float* x   = (const float*)d_in[0];
    const float* Phi = (const float*)d_in[1];
    if (n_in >= 2 && in_sizes[0] == OUT_DIM * IN_DIM &&
        in_sizes[1] == N_ROWS * IN_DIM) {
        x   = (const float*)d_in[1];
        Phi = (const float*)d_in[0];
    }
    float* out = (float*)d_out;

    build_csr<<<OUT_DIM / 8, 256>>>(Phi);

    cudaFuncSetAttribute(jl_main, cudaFuncAttributeMaxDynamicSharedMemorySize,
                         SMEM_BYTES);
    jl_main<<<dim3(N_ROWS / TILE_N, OUT_DIM / RPC), THREADS, SMEM_BYTES>>>(x, out);
}

// round 9
// speedup vs baseline: 3.3649x; 1.5399x over previous
#include <cuda_runtime.h>
#include <cstdint>

#define IN_DIM   4096
#define OUT_DIM  1024
#define N_ROWS   16384
#define NCH      16
#define CCOLS    256                    // columns per K-chunk
#define TILE_N   128                    // x rows per CTA (4 per lane)
#define XSTRIDE  148                    // words/col: 148 % 32 == 20 -> conflict-free STS.128
                                        // and 148 % 4 == 0 -> 16B-aligned LDS.128 gathers
#define COLBYTES (XSTRIDE * 4)          // 592
#define DUMMY_OFF (CCOLS * COLBYTES)    // 151552: zero column
#define XS_WORDS  ((CCOLS + 1) * XSTRIDE)   // 38036 words = 152144 B
#define ENT_OFF   152144                // 16B aligned
#define SLOT      16                    // entries per (row,chunk); Poisson(2.5) tail ~1e-8
#define ENT_BYTES (256 * SLOT * 4)      // 16384
#define CNT_OFF   (ENT_OFF + ENT_BYTES)
#define SMEM_TOTAL (CNT_OFF + 256)      // 168784 B
#define OUT_STRIDE 257
#define THREADS  1024                   // 32 warps, regs hard-capped at 64
#define RPC      256                    // out-rows per CTA
#define RPW      8                      // out-rows per warp -> float4 acc[8] = 32 regs

// Chunk-major fixed slots: entry = local_col*592 | sign<<31; dummy -> zero col
__device__ uint32_t g_ents2[NCH * OUT_DIM * SLOT];   // 1 MB, L2-resident
__device__ uint8_t  g_pc[NCH * OUT_DIM];             // pair count per (chunk,row)
__device__ float    g_mag;

// ---------------------------------------------------------------------------
// Build: one warp per output row; per-chunk fixed slots, padded to even count.
// Deterministic (ballot/popc in column order).
// ---------------------------------------------------------------------------
__global__ void __launch_bounds__(256) build_csr(const float* __restrict__ Phi) {
    const int row  = blockIdx.x * 8 + (threadIdx.x >> 5);
    const int lane = threadIdx.x & 31;
    if (row >= OUT_DIM) return;
    const float* pr = Phi + (size_t)row * IN_DIM;

    for (int k = 0; k < NCH; ++k) {
        uint32_t* slot = g_ents2 + ((size_t)k * OUT_DIM + row) * SLOT;
        int pos = 0;
        for (int c0 = k * CCOLS; c0 < (k + 1) * CCOLS; c0 += 32) {
            float v = pr[c0 + lane];
            unsigned m = __ballot_sync(0xffffffffu, v != 0.0f);
            if (v != 0.0f) {
                int p = pos + __popc(m & ((1u << lane) - 1u));
                if (p < SLOT)
                    slot[p] = (uint32_t)((c0 + lane) & (CCOLS - 1)) * COLBYTES
                            | (__float_as_uint(v) & 0x80000000u);
                g_mag = fabsf(v);           // identical value from every writer
            }
            pos += __popc(m);
        }
        if (pos & 1) {                      // pad to even with dummy (zero col)
            if (lane == 0 && pos < SLOT) slot[pos] = DUMMY_OFF;
            pos++;
        }
        if (pos > SLOT) pos = SLOT;         // statistically unreachable clamp
        if (lane == 0) g_pc[k * OUT_DIM + row] = (uint8_t)(pos >> 1);
    }
}

// ---------------------------------------------------------------------------
// Main: CTA = (128 x-rows, 256 out-rows). Lane l gathers rows 4l..4l+3 (LDS.128).
// Staging: warp w owns rows 4w..4w+3; lane = column -> coalesced LDG.32,
// conflict-free STS.128 col-vectors. Entries staged in smem per chunk.
// ---------------------------------------------------------------------------
__global__ void __launch_bounds__(THREADS, 1) jl_main(const float* __restrict__ x,
                                                      float* __restrict__ out) {
    extern __shared__ float xs[];
    char* sm = (char*)xs;
    const int tid  = threadIdx.x;
    const int lane = tid & 31;
    const int w    = tid >> 5;
    const int rb   = blockIdx.x * RPC;     // r-split: schedule-adjacent CTAs share x
    const int n0   = blockIdx.y * TILE_N;
    const int r0l  = w * RPW;              // local out-row base for this warp

    const unsigned mb = __float_as_uint(g_mag);
    const char* xb = sm + lane * 16;       // this lane's 4-row base

    if (tid < XSTRIDE) xs[CCOLS * XSTRIDE + tid] = 0.0f;   // zero dummy column

    float4 acc[RPW];
    #pragma unroll
    for (int i = 0; i < RPW; ++i) acc[i] = make_float4(0.f, 0.f, 0.f, 0.f);

    for (int k = 0; k < NCH; ++k) {
        __syncthreads();
        // ---- stage x chunk: rows 4w..4w+3, columns it*32+lane ----
        {
            const float* xr = x + (size_t)(n0 + 4 * w) * IN_DIM + k * CCOLS;
            #pragma unroll
            for (int it = 0; it < CCOLS / 32; ++it) {
                const int c = it * 32 + lane;
                float f0 = xr[c];
                float f1 = xr[c + IN_DIM];
                float f2 = xr[c + 2 * IN_DIM];
                float f3 = xr[c + 3 * IN_DIM];
                *(float4*)&xs[c * XSTRIDE + 4 * w] = make_float4(f0, f1, f2, f3);
            }
        }
        // ---- stage entry slots (16 KB) + pair counts (256 B) ----
        ((uint4*)(sm + ENT_OFF))[tid] =
            ((const uint4*)g_ents2)[((size_t)k * OUT_DIM + rb) * (SLOT / 4) + tid];
        if (tid < 16)
            ((uint4*)(sm + CNT_OFF))[tid] =
                *((const uint4*)(g_pc + k * OUT_DIM + rb) + tid);
        __syncthreads();

        // ---- gather: warp sweeps its 8 out-rows ----
        const uint8_t* cnts = (const uint8_t*)(sm + CNT_OFF) + r0l;
        #pragma unroll
        for (int rr = 0; rr < RPW; ++rr) {
            const int pairs = cnts[rr];
            const uint2* eb = (const uint2*)(sm + ENT_OFF + (r0l + rr) * (SLOT * 4));
            float4 a = acc[rr];
            for (int p = 0; p < pairs; ++p) {
                const uint2 e = eb[p];                       // LDS.64 broadcast
                {
                    float m0 = __uint_as_float(mb | (e.x & 0x80000000u));
                    float4 f = *(const float4*)(xb + (e.x & 0x7FFFFFFFu));
                    a.x = fmaf(f.x, m0, a.x); a.y = fmaf(f.y, m0, a.y);
                    a.z = fmaf(f.z, m0, a.z); a.w = fmaf(f.w, m0, a.w);
                }
                {
                    float m1 = __uint_as_float(mb | (e.y & 0x80000000u));
                    float4 f = *(const float4*)(xb + (e.y & 0x7FFFFFFFu));
                    a.x = fmaf(f.x, m1, a.x); a.y = fmaf(f.y, m1, a.y);
                    a.z = fmaf(f.z, m1, a.z); a.w = fmaf(f.w, m1, a.w);
                }
            }
            acc[rr] = a;
        }
    }

    // ---- epilogue: stage via smem (stride 257), then coalesced float4 STG ----
    __syncthreads();
    #pragma unroll
    for (int rr = 0; rr < RPW; ++rr) {
        const int rl = r0l + rr;
        float4 a = acc[rr];
        xs[(4 * lane + 0) * OUT_STRIDE + rl] = a.x;
        xs[(4 * lane + 1) * OUT_STRIDE + rl] = a.y;
        xs[(4 * lane + 2) * OUT_STRIDE + rl] = a.z;
        xs[(4 * lane + 3) * OUT_STRIDE + rl] = a.w;
    }
    __syncthreads();
    {
        const int mq = tid & 63;                 // 64 col-quads cover 256 r
        #pragma unroll
        for (int row = tid >> 6; row < TILE_N; row += 16) {
            float4 v;
            v.x = xs[row * OUT_STRIDE + 4 * mq + 0];
            v.y = xs[row * OUT_STRIDE + 4 * mq + 1];
            v.z = xs[row * OUT_STRIDE + 4 * mq + 2];
            v.w = xs[row * OUT_STRIDE + 4 * mq + 3];
            *(float4*)(out + (size_t)(n0 + row) * OUT_DIM + rb + 4 * mq) = v;
        }
    }
}

// ---------------------------------------------------------------------------
extern "C" void kernel_launch(void* const* d_in, const int* in_sizes, int n_in,
                              void* d_out, int out_size) {
    const float* x   = (const float*)d_in[0];
    const float* Phi = (const float*)d_in[1];
    if (n_in >= 2 && in_sizes[0] == OUT_DIM * IN_DIM &&
        in_sizes[1] == N_ROWS * IN_DIM) {
        x   = (const float*)d_in[1];
        Phi = (const float*)d_in[0];
    }
    float* out = (float*)d_out;

    build_csr<<<OUT_DIM / 8, 256>>>(Phi);

    cudaFuncSetAttribute(jl_main, cudaFuncAttributeMaxDynamicSharedMemorySize,
                         SMEM_TOTAL);
    // grid.x = r-splits (schedule-adjacent CTAs share the same x tile via L2)
    jl_main<<<dim3(OUT_DIM / RPC, N_ROWS / TILE_N), THREADS, SMEM_TOTAL>>>(x, out);
}